// round 3
// baseline (speedup 1.0000x reference)
#include <cuda_runtime.h>

// HexaToParallelogram: out[bs, q, r] = hexa[bs, pix(q,r)] for valid hex cells
// (|q+r| <= 18), 0.0 for corner cells. In: [32768, 1039] fp32 (first 1027 used),
// out: [32768, 1369] fp32.
//
// Closed-form lookup (no table anywhere):
//   qi = j/37, ri = j%37, valid iff 18 <= qi+ri <= 54
//   qi <= 18: pix = 19*qi + qi*(qi-1)/2 + (ri + qi - 18)
//   qi >  18: pix = 495 + 37*(qi-18) - (qi-18)*(qi-19)/2 + ri
//
// Block layout: each block stages R=8 input rows to smem (vectorized LDG.128),
// then each thread owns one output column j for all 8 rows:
//   - one src_index() per j (amortized over 8 elements)
//   - gathers: stride-1 across lanes -> conflict-free LDS, immediate row offsets
//   - stores: coalesced STG.32, immediate row offsets

#define W          37
#define CELLS      1369              // 37*37
#define IN_STRIDE  1039
#define TPB        256
#define R          8                 // rows per block
#define IN_FLOATS  (R * IN_STRIDE)   // 8312  (== 0 mod 4)

__device__ __forceinline__ int src_index(int j) {
    int qi = j / W;              // constant divisor -> mulhi
    int ri = j - qi * W;
    int s = qi + ri;
    if (s < 18 || s > 54) return -1;   // padding corner
    if (qi <= 18) {
        return 19 * qi + (qi * (qi - 1)) / 2 + (ri + qi - 18);
    } else {
        int q = qi - 18;
        return 495 + 37 * q - (q * (q - 1)) / 2 + ri;
    }
}

__global__ void __launch_bounds__(TPB)
hexa_stage_kernel(const float* __restrict__ hexa,
                  float* __restrict__ out) {
    __shared__ float s_in[IN_FLOATS];

    const unsigned row0 = blockIdx.x * R;

    // Phase 1: bulk copy 8 input rows, fully vectorized (8*1039 % 4 == 0, base aligned)
    const float4* __restrict__ gin = (const float4*)(hexa + (size_t)row0 * IN_STRIDE);
    float4* s_in4 = (float4*)s_in;
    #pragma unroll 5
    for (int i = threadIdx.x; i < IN_FLOATS / 4; i += TPB) {
        s_in4[i] = gin[i];
    }
    __syncthreads();

    // Phase 2: one column j per thread, all 8 rows.
    float* __restrict__ ob_base = out + (size_t)row0 * CELLS;
    for (int j = threadIdx.x; j < CELLS; j += TPB) {
        int src = src_index(j);
        int sc  = src < 0 ? 0 : src;        // clamped for safe predicated load
        float* ob = ob_base + j;
        float v[R];
        #pragma unroll
        for (int lr = 0; lr < R; lr++) {
            float t = s_in[lr * IN_STRIDE + sc];
            v[lr] = (src >= 0) ? t : 0.0f;
        }
        #pragma unroll
        for (int lr = 0; lr < R; lr++) {
            ob[lr * CELLS] = v[lr];
        }
    }
}

// Fallback scalar kernel for any tail rows (total_rows % R != 0)
__global__ void __launch_bounds__(TPB)
hexa_tail_kernel(const float* __restrict__ hexa,
                 float* __restrict__ out,
                 int row_start, int total_rows) {
    int j = blockIdx.x * TPB + threadIdx.x;
    if (j >= CELLS) return;
    int src = src_index(j);
    for (int row = row_start + blockIdx.y; row < total_rows; row += gridDim.y) {
        float v = (src >= 0) ? __ldg(hexa + (size_t)row * IN_STRIDE + src) : 0.0f;
        out[(size_t)row * CELLS + j] = v;
    }
}

extern "C" void kernel_launch(void* const* d_in, const int* in_sizes, int n_in,
                              void* d_out, int out_size) {
    const float* hexa = (const float*)d_in[0];
    float* out = (float*)d_out;

    int total_rows = out_size / CELLS;       // 32768
    int full_blocks = total_rows / R;        // 4096
    if (full_blocks > 0) {
        hexa_stage_kernel<<<full_blocks, TPB>>>(hexa, out);
    }
    int done = full_blocks * R;
    if (done < total_rows) {
        dim3 grid((CELLS + TPB - 1) / TPB, total_rows - done);
        hexa_tail_kernel<<<grid, TPB>>>(hexa, out, done, total_rows);
    }
}

// round 4
// speedup vs baseline: 1.0084x; 1.0084x over previous
#include <cuda_runtime.h>

// HexaToParallelogram: out[bs, q, r] = hexa[bs, pix(q,r)] for valid hex cells
// (|q+r| <= 18), 0.0 for corner cells. In: [32768, 1039] fp32 (first 1027 used),
// out: [32768, 1369] fp32.
//
// Closed-form lookup:
//   qi = j/37, ri = j%37, valid iff 18 <= qi+ri <= 54
//   qi <= 18: pix = 19*qi + qi*(qi-1)/2 + (ri + qi - 18)
//   qi >  18: pix = 495 + 37*(qi-18) - (qi-18)*(qi-19)/2 + ri
//
// Layout: block stages R=8 input rows into smem split by word residue class
// (i%4 planes) so that float4-granular output work (thread -> 4 consecutive
// output floats, lanes 4 apart -> gather word-stride 4) reads each class at
// consecutive offsets: conflict-free LDS, while stores stay STG.128.

#define W          37
#define CELLS      1369              // 37*37
#define IN_STRIDE  1039
#define TPB        256
#define R          8                 // rows per block
#define IN_FLOATS  (R * IN_STRIDE)   // 8312  (== 0 mod 4)
#define IN_VEC     (IN_FLOATS / 4)   // 2078
#define OUT_VEC    (R * CELLS / 4)   // 2738
#define TBL_PLANE  344               // ceil(1369/4) + pad

__device__ __forceinline__ int src_index(int j) {
    int qi = j / W;              // constant divisor -> mulhi
    int ri = j - qi * W;
    int s = qi + ri;
    if (s < 18 || s > 54) return -1;   // padding corner
    if (qi <= 18) {
        return 19 * qi + (qi * (qi - 1)) / 2 + (ri + qi - 18);
    } else {
        int q = qi - 18;
        return 495 + 37 * q - (q * (q - 1)) / 2 + ri;
    }
}

__global__ void __launch_bounds__(TPB)
hexa_stage_kernel(const float* __restrict__ hexa,
                  float* __restrict__ out) {
    __shared__ float s_in[4][IN_VEC];     // residue-class planes of staged input
    __shared__ short s_tbl[4][TBL_PLANE]; // residue-class planes of src table

    const unsigned row0 = blockIdx.x * R;

    // Phase 1a: bulk copy 8 input rows (LDG.128), scatter words to class planes.
    // Flat word i = 4*iv + c  ->  s_in[c][iv]. Lane-adjacent iv => conflict-free STS.32.
    const float4* __restrict__ gin = (const float4*)(hexa + (size_t)row0 * IN_STRIDE);
    #pragma unroll 4
    for (int iv = threadIdx.x; iv < IN_VEC; iv += TPB) {
        float4 t = gin[iv];
        s_in[0][iv] = t.x;
        s_in[1][iv] = t.y;
        s_in[2][iv] = t.z;
        s_in[3][iv] = t.w;
    }

    // Phase 1b: build src table in class planes (overlaps with load latency).
    for (int j = threadIdx.x; j < CELLS; j += TPB) {
        s_tbl[j & 3][j >> 2] = (short)src_index(j);
    }
    __syncthreads();

    // Phase 2: one float4 of output per thread-iter, STG.128 stores.
    float4* __restrict__ gout = (float4*)(out + (size_t)row0 * CELLS);
    #pragma unroll 2
    for (int v = threadIdx.x; v < OUT_VEC; v += TPB) {
        int f  = 4 * v;
        int lr = f / CELLS;               // constant divisor
        int j0 = f - lr * CELLS;
        float4 o;
        float* op = (float*)&o;
        #pragma unroll
        for (int e = 0; e < 4; e++) {
            int j = j0 + e;
            int lrr = lr;
            if (j >= CELLS) { j -= CELLS; lrr++; }
            int src = s_tbl[j & 3][j >> 2];
            int i = lrr * IN_STRIDE + (src < 0 ? 0 : src);
            float t = s_in[i & 3][i >> 2];
            op[e] = (src < 0) ? 0.0f : t;
        }
        gout[v] = o;
    }
}

// Fallback scalar kernel for any tail rows (total_rows % R != 0)
__global__ void __launch_bounds__(TPB)
hexa_tail_kernel(const float* __restrict__ hexa,
                 float* __restrict__ out,
                 int row_start, int total_rows) {
    int j = blockIdx.x * TPB + threadIdx.x;
    if (j >= CELLS) return;
    int src = src_index(j);
    for (int row = row_start + blockIdx.y; row < total_rows; row += gridDim.y) {
        float v = (src >= 0) ? __ldg(hexa + (size_t)row * IN_STRIDE + src) : 0.0f;
        out[(size_t)row * CELLS + j] = v;
    }
}

extern "C" void kernel_launch(void* const* d_in, const int* in_sizes, int n_in,
                              void* d_out, int out_size) {
    const float* hexa = (const float*)d_in[0];
    float* out = (float*)d_out;

    int total_rows = out_size / CELLS;       // 32768
    int full_blocks = total_rows / R;        // 4096
    if (full_blocks > 0) {
        hexa_stage_kernel<<<full_blocks, TPB>>>(hexa, out);
    }
    int done = full_blocks * R;
    if (done < total_rows) {
        dim3 grid((CELLS + TPB - 1) / TPB, total_rows - done);
        hexa_tail_kernel<<<grid, TPB>>>(hexa, out, done, total_rows);
    }
}

// round 5
// speedup vs baseline: 1.1850x; 1.1751x over previous
#include <cuda_runtime.h>

// HexaToParallelogram: out[bs, q, r] = hexa[bs, pix(q,r)] for valid hex cells
// (|q+r| <= 18), 0.0 for corner cells. In: [32768, 1039] fp32 (first 1027 used),
// out: [32768, 1369] fp32.
//
// Direct gmem->gmem copy. Since 1369 % 4 == 1, output float4 alignment repeats
// every 4 bs-rows (supertile = 4*1369 = 5476 floats = 1369 float4s). Each thread
// owns one float4 slot v of the supertile, computes its (row-in-supertile, src,
// valid) tuple ONCE, then grid-strides over supertiles with only pointer bumps:
// 4 predicated LDG.32 (contiguous across lanes) + 1 STG.128 per iteration.

#define W          37
#define CELLS      1369              // 37*37
#define IN_STRIDE  1039
#define TPB        256
#define SLOTS      1369              // float4 slots per supertile
#define GROUPS     512               // concurrent supertile streams

__device__ __forceinline__ int src_index(int j) {
    int qi = j / W;              // constant divisor -> mulhi
    int ri = j - qi * W;
    int s = qi + ri;
    if (s < 18 || s > 54) return -1;   // padding corner
    if (qi <= 18) {
        return 19 * qi + (qi * (qi - 1)) / 2 + (ri + qi - 18);
    } else {
        int q = qi - 18;
        return 495 + 37 * q - (q * (q - 1)) / 2 + ri;
    }
}

__global__ void __launch_bounds__(TPB)
hexa_direct_kernel(const float* __restrict__ hexa,
                   float* __restrict__ out,
                   int n_super) {
    int t = blockIdx.x * TPB + threadIdx.x;
    if (t >= SLOTS * GROUPS) return;
    int v = t % SLOTS;           // float4 slot within supertile (one-time div)
    int s = t / SLOTS;           // starting supertile
    if (s >= n_super) return;

    // One-time setup: resolve the 4 elements of this slot.
    int f  = 4 * v;              // flat float index in supertile [0, 5476)
    int lr = f / CELLS;          // row within supertile (0..3)
    int j0 = f - lr * CELLS;

    int  off[4];                 // input offset within supertile (floats)
    bool val[4];
    #pragma unroll
    for (int e = 0; e < 4; e++) {
        int j = j0 + e;
        int lrr = lr;
        if (j >= CELLS) { j -= CELLS; lrr++; }
        int src = src_index(j);
        val[e] = (src >= 0);
        off[e] = lrr * IN_STRIDE + (src >= 0 ? src : 0);
    }

    const float* __restrict__ ip = hexa + (size_t)s * (4 * IN_STRIDE);
    float4* __restrict__ op = (float4*)(out + (size_t)s * (4 * CELLS)) + v;

    const size_t ip_step = (size_t)GROUPS * (4 * IN_STRIDE);
    const size_t op_step = (size_t)GROUPS * CELLS;   // in float4s

    #pragma unroll 2
    for (; s < n_super; s += GROUPS) {
        float4 o;
        o.x = val[0] ? __ldg(ip + off[0]) : 0.0f;
        o.y = val[1] ? __ldg(ip + off[1]) : 0.0f;
        o.z = val[2] ? __ldg(ip + off[2]) : 0.0f;
        o.w = val[3] ? __ldg(ip + off[3]) : 0.0f;
        *op = o;
        ip += ip_step;
        op += op_step;
    }
}

// Fallback scalar kernel for any tail rows (total_rows % 4 != 0)
__global__ void __launch_bounds__(TPB)
hexa_tail_kernel(const float* __restrict__ hexa,
                 float* __restrict__ out,
                 int row_start, int total_rows) {
    int j = blockIdx.x * TPB + threadIdx.x;
    if (j >= CELLS) return;
    int src = src_index(j);
    for (int row = row_start + blockIdx.y; row < total_rows; row += gridDim.y) {
        float v = (src >= 0) ? __ldg(hexa + (size_t)row * IN_STRIDE + src) : 0.0f;
        out[(size_t)row * CELLS + j] = v;
    }
}

extern "C" void kernel_launch(void* const* d_in, const int* in_sizes, int n_in,
                              void* d_out, int out_size) {
    const float* hexa = (const float*)d_in[0];
    float* out = (float*)d_out;

    int total_rows = out_size / CELLS;       // 32768
    int n_super = total_rows / 4;            // 8192
    if (n_super > 0) {
        int threads = SLOTS * GROUPS;        // 700928
        int blocks = (threads + TPB - 1) / TPB;  // 2738
        hexa_direct_kernel<<<blocks, TPB>>>(hexa, out, n_super);
    }
    int done = n_super * 4;
    if (done < total_rows) {
        dim3 grid((CELLS + TPB - 1) / TPB, total_rows - done);
        hexa_tail_kernel<<<grid, TPB>>>(hexa, out, done, total_rows);
    }
}